// round 1
// baseline (speedup 1.0000x reference)
#include <cuda_runtime.h>
#include <cstdint>

#define NN   100000
#define NE   3200000
#define FIN  128
#define HID  16
#define ND   2000

// ---------------- scratch (no allocs allowed) ----------------
__device__ __align__(16) float g_dinv[NN];          // deg -> dinv (in place)
__device__ __align__(16) float g_hpre[NN * HID];    // h@W (pre-aggregation)
__device__ __align__(16) float g_agg [NN * HID];    // aggregated output per layer
__device__ __align__(16) float g_tmp [ND * HID];    // hd @ predictor

// ---------------- degree / norm ----------------
__global__ void k_deg_init() {
    int i = blockIdx.x * 256 + threadIdx.x;
    if (i < NN) g_dinv[i] = 1.0f;   // self-loop contributes 1 to deg
}

__global__ void k_deg_accum(const int* __restrict__ dst) {
    int t = blockIdx.x * 256 + threadIdx.x;
    int base = t * 4;
    if (base < NE) {
        int4 d = *reinterpret_cast<const int4*>(dst + base);
        atomicAdd(g_dinv + d.x, 1.0f);
        atomicAdd(g_dinv + d.y, 1.0f);
        atomicAdd(g_dinv + d.z, 1.0f);
        atomicAdd(g_dinv + d.w, 1.0f);
    }
}

__global__ void k_rsqrt() {
    int i = blockIdx.x * 256 + threadIdx.x;
    if (i < NN) g_dinv[i] = rsqrtf(g_dinv[i]);   // deg >= 1 always
}

// ---------------- GEMM1: g_hpre = x @ W1  (100k x 128 @ 128 x 16) ----------------
// 64 nodes per block, 4 threads per node (4 output cols each).
// x tile staged in smem with stride 132 (pad) for conflict-free row reads.
__global__ void k_gemm1(const float* __restrict__ x, const float* __restrict__ W1) {
    __shared__ float W1s[FIN * HID];       // 8 KB
    __shared__ float xs[64 * 132];         // ~33.8 KB padded
    int tid = threadIdx.x;

    for (int i = tid; i < FIN * HID / 4; i += 256)
        reinterpret_cast<float4*>(W1s)[i] = reinterpret_cast<const float4*>(W1)[i];

    int nbase = blockIdx.x * 64;
    for (int i = tid; i < 64 * 32; i += 256) {
        int row = i >> 5, c4 = i & 31;
        if (nbase + row < NN)
            reinterpret_cast<float4*>(xs + row * 132)[c4] =
                reinterpret_cast<const float4*>(x + (size_t)(nbase + row) * FIN)[c4];
    }
    __syncthreads();

    int node = tid >> 2;
    int jc   = (tid & 3) * 4;
    if (nbase + node >= NN) return;
    const float* xr = xs + node * 132;
    float4 acc = make_float4(0.f, 0.f, 0.f, 0.f);
#pragma unroll 8
    for (int k = 0; k < FIN; k++) {
        float xv = xr[k];
        float4 w = *reinterpret_cast<const float4*>(W1s + k * HID + jc);
        acc.x += xv * w.x; acc.y += xv * w.y; acc.z += xv * w.z; acc.w += xv * w.w;
    }
    *reinterpret_cast<float4*>(g_hpre + (size_t)(nbase + node) * HID + jc) = acc;
}

// ---------------- self-loop + bias init: g_agg = b + dinv^2 * g_hpre ----------------
__global__ void k_self_init(const float* __restrict__ b) {
    int idx = blockIdx.x * 256 + threadIdx.x;
    if (idx < NN * HID) {
        int n = idx >> 4, j = idx & 15;
        float di = g_dinv[n];
        g_agg[idx] = b[j] + di * di * g_hpre[idx];
    }
}

// ---------------- edge scatter: g_agg[dst] += dinv[s]*dinv[d] * g_hpre[src] ----------------
// 4 lanes per edge; each lane moves one float4 with a single v4 RED.
__global__ void k_edge(const int* __restrict__ src, const int* __restrict__ dst) {
    int gid = blockIdx.x * 256 + threadIdx.x;
    int e = gid >> 2;
    if (e >= NE) return;
    int c = (gid & 3) * 4;
    int s = __ldg(src + e);
    int d = __ldg(dst + e);
    float w = __ldg(g_dinv + s) * __ldg(g_dinv + d);
    float4 v = *reinterpret_cast<const float4*>(g_hpre + (size_t)s * HID + c);
    float* p = g_agg + (size_t)d * HID + c;
    asm volatile("red.global.add.v4.f32 [%0], {%1,%2,%3,%4};"
                 :: "l"(__cvta_generic_to_global(p)),
                    "f"(v.x * w), "f"(v.y * w), "f"(v.z * w), "f"(v.w * w)
                 : "memory");
}

// ---------------- GEMM2: g_hpre = relu(g_agg) @ W2  (16x16) ----------------
__global__ void k_gemm2(const float* __restrict__ W2) {
    __shared__ float W2s[HID * HID];
    int tid = threadIdx.x;
    W2s[tid] = W2[tid];   // blockDim == 256 == HID*HID
    __syncthreads();
    int n = blockIdx.x * 256 + tid;
    if (n >= NN) return;

    float row[HID];
    const float4* rv = reinterpret_cast<const float4*>(g_agg + (size_t)n * HID);
#pragma unroll
    for (int q = 0; q < 4; q++) {
        float4 v = rv[q];
        row[q * 4 + 0] = fmaxf(v.x, 0.f);
        row[q * 4 + 1] = fmaxf(v.y, 0.f);
        row[q * 4 + 2] = fmaxf(v.z, 0.f);
        row[q * 4 + 3] = fmaxf(v.w, 0.f);
    }
    float4 acc[4];
#pragma unroll
    for (int q = 0; q < 4; q++) acc[q] = make_float4(0.f, 0.f, 0.f, 0.f);
#pragma unroll
    for (int k = 0; k < HID; k++) {
        float hv = row[k];
#pragma unroll
        for (int q = 0; q < 4; q++) {
            float4 w = *reinterpret_cast<const float4*>(W2s + k * HID + q * 4);
            acc[q].x += hv * w.x; acc[q].y += hv * w.y;
            acc[q].z += hv * w.z; acc[q].w += hv * w.w;
        }
    }
    float4* ov = reinterpret_cast<float4*>(g_hpre + (size_t)n * HID);
#pragma unroll
    for (int q = 0; q < 4; q++) ov[q] = acc[q];
}

// ---------------- tmp = hd @ predictor (2000x16 @ 16x16), hd = g_agg[:2000] ----------------
__global__ void k_pred1(const float* __restrict__ P) {
    __shared__ float Ps[HID * HID];
    int tid = threadIdx.x;
    Ps[tid] = P[tid];
    __syncthreads();
    int gid = blockIdx.x * 256 + tid;   // < ND*HID
    int i = gid >> 4, j = gid & 15;
    float acc = 0.f;
    const float* hr = g_agg + (size_t)i * HID;
#pragma unroll
    for (int k = 0; k < HID; k++) acc += hr[k] * Ps[k * HID + j];
    g_tmp[gid] = acc;
}

// ---------------- out[i][j] = dot(tmp[i,:], hd[j,:])  (2000 x 2000) ----------------
__global__ void k_out(float* __restrict__ out) {
    __shared__ float ts[16][17];
    __shared__ float hs[16][17];
    int tid = threadIdx.x;
    int il = tid >> 4, jl = tid & 15;
    int ib = blockIdx.y * 16, jb = blockIdx.x * 16;
    ts[il][jl] = g_tmp[(size_t)(ib + il) * HID + jl];
    hs[il][jl] = g_agg[(size_t)(jb + il) * HID + jl];
    __syncthreads();
    float acc = 0.f;
#pragma unroll
    for (int k = 0; k < HID; k++) acc += ts[il][k] * hs[jl][k];
    out[(size_t)(ib + il) * ND + jb + jl] = acc;
}

// ---------------- launch ----------------
extern "C" void kernel_launch(void* const* d_in, const int* in_sizes, int n_in,
                              void* d_out, int out_size) {
    (void)in_sizes; (void)n_in; (void)out_size;
    const float* x  = (const float*)d_in[0];
    const int*   ei = (const int*)  d_in[1];
    const float* W1 = (const float*)d_in[2];
    const float* b1 = (const float*)d_in[3];
    const float* W2 = (const float*)d_in[4];
    const float* b2 = (const float*)d_in[5];
    const float* P  = (const float*)d_in[6];
    float* out = (float*)d_out;

    const int* src = ei;
    const int* dst = ei + NE;

    k_deg_init <<<(NN + 255) / 256, 256>>>();
    k_deg_accum<<<(NE / 4 + 255) / 256, 256>>>(dst);
    k_rsqrt    <<<(NN + 255) / 256, 256>>>();

    // layer 1
    k_gemm1    <<<(NN + 63) / 64, 256>>>(x, W1);
    k_self_init<<<(NN * HID + 255) / 256, 256>>>(b1);
    k_edge     <<<(NE * 4) / 256, 256>>>(src, dst);

    // layer 2
    k_gemm2    <<<(NN + 255) / 256, 256>>>(W2);
    k_self_init<<<(NN * HID + 255) / 256, 256>>>(b2);
    k_edge     <<<(NE * 4) / 256, 256>>>(src, dst);

    // decoder: out = (hd @ P) @ hd^T
    k_pred1<<<(ND * HID) / 256, 256>>>(P);
    k_out  <<<dim3(ND / 16, ND / 16), 256>>>(out);
}

// round 2
// speedup vs baseline: 1.3370x; 1.3370x over previous
#include <cuda_runtime.h>
#include <cstdint>

#define NN   100000
#define NE   3200000
#define FIN  128
#define HID  16
#define ND   2000

// ---------------- scratch (no allocs allowed) ----------------
__device__ __align__(16) float g_dinv[NN];
__device__ __align__(16) float g_hs  [NN * HID];   // dinv-scaled features (gather source)
__device__ __align__(16) float g_agg [NN * HID];   // raw aggregation (incl. self term)
__device__ __align__(16) float g_h2  [ND * HID];   // finalized layer-2 rows 0..ND
__device__ __align__(16) float g_tmp [ND * HID];   // h2 @ predictor

// ---------------- degree / norm ----------------
__global__ void k_deg_init() {
    int i = blockIdx.x * 256 + threadIdx.x;
    if (i < NN) g_dinv[i] = 1.0f;   // self-loop contributes 1 to deg
}

__global__ void k_deg_accum(const int* __restrict__ dst) {
    int t = blockIdx.x * 256 + threadIdx.x;
    int base = t * 4;
    if (base < NE) {
        int4 d = *reinterpret_cast<const int4*>(dst + base);
        atomicAdd(g_dinv + d.x, 1.0f);
        atomicAdd(g_dinv + d.y, 1.0f);
        atomicAdd(g_dinv + d.z, 1.0f);
        atomicAdd(g_dinv + d.w, 1.0f);
    }
}

__global__ void k_rsqrt() {
    int i = blockIdx.x * 256 + threadIdx.x;
    if (i < NN) g_dinv[i] = rsqrtf(g_dinv[i]);
}

// ---------------- GEMM1: g_hs = dinv * (x @ W1) ----------------
// 64 nodes/block, 4 threads/node (4 cols each), float4 x-reads from padded smem.
__global__ void k_gemm1(const float* __restrict__ x, const float* __restrict__ W1) {
    __shared__ float W1s[FIN * HID];       // 8 KB
    __shared__ float xs[64 * 132];         // 33.8 KB, stride 132 -> conflict-free
    int tid = threadIdx.x;

    for (int i = tid; i < FIN * HID / 4; i += 256)
        reinterpret_cast<float4*>(W1s)[i] = reinterpret_cast<const float4*>(W1)[i];

    int nbase = blockIdx.x * 64;
    for (int i = tid; i < 64 * 32; i += 256) {
        int row = i >> 5, c4 = i & 31;
        if (nbase + row < NN)
            reinterpret_cast<float4*>(xs + row * 132)[c4] =
                reinterpret_cast<const float4*>(x + (size_t)(nbase + row) * FIN)[c4];
    }
    __syncthreads();

    int node = tid >> 2;
    int jc   = (tid & 3) * 4;
    if (nbase + node >= NN) return;
    const float4* xr = reinterpret_cast<const float4*>(xs + node * 132);
    float4 acc = make_float4(0.f, 0.f, 0.f, 0.f);
#pragma unroll 8
    for (int k4 = 0; k4 < 32; k4++) {
        float4 xv = xr[k4];
        float4 w0 = *reinterpret_cast<const float4*>(W1s + (4 * k4 + 0) * HID + jc);
        float4 w1 = *reinterpret_cast<const float4*>(W1s + (4 * k4 + 1) * HID + jc);
        float4 w2 = *reinterpret_cast<const float4*>(W1s + (4 * k4 + 2) * HID + jc);
        float4 w3 = *reinterpret_cast<const float4*>(W1s + (4 * k4 + 3) * HID + jc);
        acc.x += xv.x * w0.x + xv.y * w1.x + xv.z * w2.x + xv.w * w3.x;
        acc.y += xv.x * w0.y + xv.y * w1.y + xv.z * w2.y + xv.w * w3.y;
        acc.z += xv.x * w0.z + xv.y * w1.z + xv.z * w2.z + xv.w * w3.z;
        acc.w += xv.x * w0.w + xv.y * w1.w + xv.z * w2.w + xv.w * w3.w;
    }
    float di = g_dinv[nbase + node];
    acc.x *= di; acc.y *= di; acc.z *= di; acc.w *= di;
    *reinterpret_cast<float4*>(g_hs + (size_t)(nbase + node) * HID + jc) = acc;
}

// ---------------- self term: g_agg = g_hs (first R rows) ----------------
__global__ void k_copy_self(int r4) {   // r4 = R*HID/4
    int i = blockIdx.x * 256 + threadIdx.x;
    if (i < r4)
        reinterpret_cast<float4*>(g_agg)[i] = reinterpret_cast<const float4*>(g_hs)[i];
}

// ---------------- edge scatter (layer 1): g_agg[dst] += g_hs[src] ----------------
__global__ void k_edge1(const int* __restrict__ src, const int* __restrict__ dst) {
    int gid = blockIdx.x * 256 + threadIdx.x;
    int e = gid >> 2;
    int c = (gid & 3) * 4;
    int s = __ldg(src + e);
    int d = __ldg(dst + e);
    float4 v = *reinterpret_cast<const float4*>(g_hs + (size_t)s * HID + c);
    float* p = g_agg + (size_t)d * HID + c;
    asm volatile("red.global.add.v4.f32 [%0], {%1,%2,%3,%4};"
                 :: "l"(__cvta_generic_to_global(p)),
                    "f"(v.x), "f"(v.y), "f"(v.z), "f"(v.w)
                 : "memory");
}

// ---------------- edge scatter (layer 2): only dst < ND matters ----------------
__global__ void k_edge2(const int* __restrict__ src, const int* __restrict__ dst) {
    int gid = blockIdx.x * 256 + threadIdx.x;
    int e = gid >> 2;
    int d = __ldg(dst + e);
    if (d >= ND) return;
    int c = (gid & 3) * 4;
    int s = __ldg(src + e);
    float4 v = *reinterpret_cast<const float4*>(g_hs + (size_t)s * HID + c);
    float* p = g_agg + (size_t)d * HID + c;
    asm volatile("red.global.add.v4.f32 [%0], {%1,%2,%3,%4};"
                 :: "l"(__cvta_generic_to_global(p)),
                    "f"(v.x), "f"(v.y), "f"(v.z), "f"(v.w)
                 : "memory");
}

// ---------------- GEMM2: g_hs = dinv * ( relu(dinv*g_agg + b1) @ W2 ) ----------------
__global__ void k_gemm2(const float* __restrict__ W2, const float* __restrict__ b1) {
    __shared__ float W2s[HID * HID];
    __shared__ float b1s[HID];
    int tid = threadIdx.x;
    W2s[tid] = W2[tid];
    if (tid < HID) b1s[tid] = b1[tid];
    __syncthreads();
    int n = blockIdx.x * 256 + tid;
    if (n >= NN) return;

    float di = g_dinv[n];
    float row[HID];
    const float4* rv = reinterpret_cast<const float4*>(g_agg + (size_t)n * HID);
#pragma unroll
    for (int q = 0; q < 4; q++) {
        float4 v = rv[q];
        row[q * 4 + 0] = fmaxf(di * v.x + b1s[q * 4 + 0], 0.f);
        row[q * 4 + 1] = fmaxf(di * v.y + b1s[q * 4 + 1], 0.f);
        row[q * 4 + 2] = fmaxf(di * v.z + b1s[q * 4 + 2], 0.f);
        row[q * 4 + 3] = fmaxf(di * v.w + b1s[q * 4 + 3], 0.f);
    }
    float4 acc[4];
#pragma unroll
    for (int q = 0; q < 4; q++) acc[q] = make_float4(0.f, 0.f, 0.f, 0.f);
#pragma unroll
    for (int k = 0; k < HID; k++) {
        float hv = row[k];
#pragma unroll
        for (int q = 0; q < 4; q++) {
            float4 w = *reinterpret_cast<const float4*>(W2s + k * HID + q * 4);
            acc[q].x += hv * w.x; acc[q].y += hv * w.y;
            acc[q].z += hv * w.z; acc[q].w += hv * w.w;
        }
    }
    float4* ov = reinterpret_cast<float4*>(g_hs + (size_t)n * HID);
#pragma unroll
    for (int q = 0; q < 4; q++) {
        acc[q].x *= di; acc[q].y *= di; acc[q].z *= di; acc[q].w *= di;
        ov[q] = acc[q];
    }
}

// ---------------- finalize layer 2 + tmp = h2 @ P ----------------
// h2[n] = dinv[n]*g_agg[n] + b2 (n < ND); writes g_h2 and g_tmp.
__global__ void k_pred1(const float* __restrict__ P, const float* __restrict__ b2) {
    __shared__ float Ps[HID * HID];
    __shared__ float h2s[16][17];
    int tid = threadIdx.x;
    Ps[tid] = P[tid];
    int gid = blockIdx.x * 256 + tid;      // < ND*HID
    int i = gid >> 4, j = gid & 15;
    int il = (tid >> 4), jl = tid & 15;
    float v = g_dinv[i] * g_agg[gid] + __ldg(b2 + j);
    g_h2[gid] = v;
    h2s[il][jl] = v;
    __syncthreads();
    float acc = 0.f;
#pragma unroll
    for (int k = 0; k < HID; k++) acc += h2s[il][k] * Ps[k * HID + j];
    g_tmp[gid] = acc;
}

// ---------------- out[i][j] = dot(tmp[i,:], h2[j,:]) ----------------
__global__ void k_out(float* __restrict__ out) {
    __shared__ float ts[16][17];
    __shared__ float hs[16][17];
    int tid = threadIdx.x;
    int il = tid >> 4, jl = tid & 15;
    int ib = blockIdx.y * 16, jb = blockIdx.x * 16;
    ts[il][jl] = g_tmp[(size_t)(ib + il) * HID + jl];
    hs[il][jl] = g_h2[(size_t)(jb + il) * HID + jl];
    __syncthreads();
    float acc = 0.f;
#pragma unroll
    for (int k = 0; k < HID; k++) acc += ts[il][k] * hs[jl][k];
    out[(size_t)(ib + il) * ND + jb + jl] = acc;
}

// ---------------- launch ----------------
extern "C" void kernel_launch(void* const* d_in, const int* in_sizes, int n_in,
                              void* d_out, int out_size) {
    (void)in_sizes; (void)n_in; (void)out_size;
    const float* x  = (const float*)d_in[0];
    const int*   ei = (const int*)  d_in[1];
    const float* W1 = (const float*)d_in[2];
    const float* b1 = (const float*)d_in[3];
    const float* W2 = (const float*)d_in[4];
    const float* b2 = (const float*)d_in[5];
    const float* P  = (const float*)d_in[6];
    float* out = (float*)d_out;

    const int* src = ei;
    const int* dst = ei + NE;

    // degree / norm
    k_deg_init <<<(NN + 255) / 256, 256>>>();
    k_deg_accum<<<NE / 4 / 256, 256>>>(dst);
    k_rsqrt    <<<(NN + 255) / 256, 256>>>();

    // layer 1
    k_gemm1    <<<(NN + 63) / 64, 256>>>(x, W1);
    k_copy_self<<<(NN * HID / 4 + 255) / 256, 256>>>(NN * HID / 4);
    k_edge1    <<<(NE * 4) / 256, 256>>>(src, dst);

    // layer 2 (only rows < ND ever consumed downstream)
    k_gemm2    <<<(NN + 255) / 256, 256>>>(W2, b1);
    k_copy_self<<<(ND * HID / 4 + 255) / 256, 256>>>(ND * HID / 4);
    k_edge2    <<<(NE * 4) / 256, 256>>>(src, dst);

    // decoder
    k_pred1<<<(ND * HID) / 256, 256>>>(P, b2);
    k_out  <<<dim3(ND / 16, ND / 16), 256>>>(out);
}

// round 3
// speedup vs baseline: 1.4076x; 1.0528x over previous
#include <cuda_runtime.h>
#include <cstdint>

#define NN   100000
#define NE   3200000
#define FIN  128
#define HID  16
#define ND   2000

// ---------------- scratch (no allocs allowed) ----------------
__device__ __align__(16) float g_dinv[NN];
__device__ __align__(16) float g_hs  [NN * HID];   // dinv-scaled features (gather source)
__device__ __align__(16) float g_agg [NN * HID];   // aggregation (self term folded in)
__device__              unsigned char g_mask[NN];  // node feeds a drug row?
__device__ __align__(16) float g_h2  [ND * HID];
__device__ __align__(16) float g_tmp [ND * HID];

// ---------------- init: deg=1 (self loop), mask = (n < ND) ----------------
__global__ void k_init() {
    int i = blockIdx.x * 256 + threadIdx.x;
    if (i < NN) {
        g_dinv[i] = 1.0f;
        g_mask[i] = (i < ND) ? 1 : 0;
    }
}

// ---------------- fused degree accumulation + mask build ----------------
__global__ void k_prep(const int* __restrict__ src, const int* __restrict__ dst) {
    int t = blockIdx.x * 256 + threadIdx.x;
    int base = t * 4;
    if (base >= NE) return;
    int4 d = *reinterpret_cast<const int4*>(dst + base);
    atomicAdd(g_dinv + d.x, 1.0f);
    atomicAdd(g_dinv + d.y, 1.0f);
    atomicAdd(g_dinv + d.z, 1.0f);
    atomicAdd(g_dinv + d.w, 1.0f);
    if (d.x < ND) g_mask[__ldg(src + base + 0)] = 1;
    if (d.y < ND) g_mask[__ldg(src + base + 1)] = 1;
    if (d.z < ND) g_mask[__ldg(src + base + 2)] = 1;
    if (d.w < ND) g_mask[__ldg(src + base + 3)] = 1;
}

__global__ void k_rsqrt() {
    int i = blockIdx.x * 256 + threadIdx.x;
    if (i < NN) g_dinv[i] = rsqrtf(g_dinv[i]);
}

// ---------------- GEMM1: g_hs = g_agg = dinv * (x @ W1) ----------------
// One node per thread (256 nodes/block). x tile staged k-transposed in smem
// (chunks of 32 k), stride 257 -> conflict-free writes AND reads.
// W row reads are warp-uniform (broadcast, no crossbar cost).
#define KC 32
#define XS_STRIDE 257
__global__ void __launch_bounds__(256) k_gemm1(const float* __restrict__ x,
                                               const float* __restrict__ W1) {
    __shared__ float W1s[FIN * HID];            // 8 KB
    __shared__ float xs[KC * XS_STRIDE];        // 32.1 KB
    int tid = threadIdx.x;
    int nbase = blockIdx.x * 256;
    int node = nbase + tid;

    for (int i = tid; i < FIN * HID / 4; i += 256)
        reinterpret_cast<float4*>(W1s)[i] = reinterpret_cast<const float4*>(W1)[i];

    float acc[HID];
#pragma unroll
    for (int j = 0; j < HID; j++) acc[j] = 0.f;

    for (int c = 0; c < FIN / KC; c++) {
        __syncthreads();
        // load chunk transposed: xs[k][row] = x[nbase+row][c*32+k]
#pragma unroll
        for (int it = 0; it < 8; it++) {
            int i = tid + it * 256;          // 0..2047
            int row = i >> 3;                // 0..255
            int f4  = i & 7;                 // 0..7
            if (nbase + row < NN) {
                float4 v = *reinterpret_cast<const float4*>(
                    x + (size_t)(nbase + row) * FIN + c * KC + f4 * 4);
                xs[(f4 * 4 + 0) * XS_STRIDE + row] = v.x;
                xs[(f4 * 4 + 1) * XS_STRIDE + row] = v.y;
                xs[(f4 * 4 + 2) * XS_STRIDE + row] = v.z;
                xs[(f4 * 4 + 3) * XS_STRIDE + row] = v.w;
            }
        }
        __syncthreads();
        const float* Wc = W1s + c * KC * HID;
#pragma unroll
        for (int k = 0; k < KC; k++) {
            float xv = xs[k * XS_STRIDE + tid];
            const float4* wr = reinterpret_cast<const float4*>(Wc + k * HID);
            float4 w0 = wr[0], w1 = wr[1], w2 = wr[2], w3 = wr[3];
            acc[0]  += xv * w0.x; acc[1]  += xv * w0.y; acc[2]  += xv * w0.z; acc[3]  += xv * w0.w;
            acc[4]  += xv * w1.x; acc[5]  += xv * w1.y; acc[6]  += xv * w1.z; acc[7]  += xv * w1.w;
            acc[8]  += xv * w2.x; acc[9]  += xv * w2.y; acc[10] += xv * w2.z; acc[11] += xv * w2.w;
            acc[12] += xv * w3.x; acc[13] += xv * w3.y; acc[14] += xv * w3.z; acc[15] += xv * w3.w;
        }
    }
    if (node >= NN) return;
    float di = g_dinv[node];
#pragma unroll
    for (int q = 0; q < 4; q++) {
        float4 v = make_float4(acc[q*4+0]*di, acc[q*4+1]*di, acc[q*4+2]*di, acc[q*4+3]*di);
        *reinterpret_cast<float4*>(g_hs  + (size_t)node * HID + q * 4) = v;
        *reinterpret_cast<float4*>(g_agg + (size_t)node * HID + q * 4) = v;   // self term
    }
}

// ---------------- edge scatter (layer 1): only masked dst matter ----------------
__global__ void k_edge1(const int* __restrict__ src, const int* __restrict__ dst) {
    int gid = blockIdx.x * 256 + threadIdx.x;
    int e = gid >> 2;
    int d = __ldg(dst + e);
    if (!g_mask[d]) return;
    int c = (gid & 3) * 4;
    int s = __ldg(src + e);
    float4 v = *reinterpret_cast<const float4*>(g_hs + (size_t)s * HID + c);
    float* p = g_agg + (size_t)d * HID + c;
    asm volatile("red.global.add.v4.f32 [%0], {%1,%2,%3,%4};"
                 :: "l"(__cvta_generic_to_global(p)),
                    "f"(v.x), "f"(v.y), "f"(v.z), "f"(v.w)
                 : "memory");
}

// ---------------- edge scatter (layer 2): only dst < ND ----------------
__global__ void k_edge2(const int* __restrict__ src, const int* __restrict__ dst) {
    int gid = blockIdx.x * 256 + threadIdx.x;
    int e = gid >> 2;
    int d = __ldg(dst + e);
    if (d >= ND) return;
    int c = (gid & 3) * 4;
    int s = __ldg(src + e);
    float4 v = *reinterpret_cast<const float4*>(g_hs + (size_t)s * HID + c);
    float* p = g_agg + (size_t)d * HID + c;
    asm volatile("red.global.add.v4.f32 [%0], {%1,%2,%3,%4};"
                 :: "l"(__cvta_generic_to_global(p)),
                    "f"(v.x), "f"(v.y), "f"(v.z), "f"(v.w)
                 : "memory");
}

// ---------------- GEMM2 (masked nodes only): ----------------
// g_hs[n] = dinv*( relu(dinv*agg1 + b1) @ W2 );  g_agg[n<ND] = g_hs[n] (self term)
__global__ void k_gemm2(const float* __restrict__ W2, const float* __restrict__ b1) {
    __shared__ float W2s[HID * HID];
    __shared__ float b1s[HID];
    int tid = threadIdx.x;
    W2s[tid] = W2[tid];
    if (tid < HID) b1s[tid] = b1[tid];
    __syncthreads();
    int n = blockIdx.x * 256 + tid;
    if (n >= NN) return;
    if (!g_mask[n]) return;

    float di = g_dinv[n];
    float row[HID];
    const float4* rv = reinterpret_cast<const float4*>(g_agg + (size_t)n * HID);
#pragma unroll
    for (int q = 0; q < 4; q++) {
        float4 v = rv[q];
        row[q * 4 + 0] = fmaxf(di * v.x + b1s[q * 4 + 0], 0.f);
        row[q * 4 + 1] = fmaxf(di * v.y + b1s[q * 4 + 1], 0.f);
        row[q * 4 + 2] = fmaxf(di * v.z + b1s[q * 4 + 2], 0.f);
        row[q * 4 + 3] = fmaxf(di * v.w + b1s[q * 4 + 3], 0.f);
    }
    float4 acc[4];
#pragma unroll
    for (int q = 0; q < 4; q++) acc[q] = make_float4(0.f, 0.f, 0.f, 0.f);
#pragma unroll
    for (int k = 0; k < HID; k++) {
        float hv = row[k];
#pragma unroll
        for (int q = 0; q < 4; q++) {
            float4 w = *reinterpret_cast<const float4*>(W2s + k * HID + q * 4);
            acc[q].x += hv * w.x; acc[q].y += hv * w.y;
            acc[q].z += hv * w.z; acc[q].w += hv * w.w;
        }
    }
#pragma unroll
    for (int q = 0; q < 4; q++) {
        acc[q].x *= di; acc[q].y *= di; acc[q].z *= di; acc[q].w *= di;
        *reinterpret_cast<float4*>(g_hs + (size_t)n * HID + q * 4) = acc[q];
        if (n < ND)
            *reinterpret_cast<float4*>(g_agg + (size_t)n * HID + q * 4) = acc[q];
    }
}

// ---------------- finalize layer 2 + tmp = h2 @ P ----------------
__global__ void k_pred1(const float* __restrict__ P, const float* __restrict__ b2) {
    __shared__ float Ps[HID * HID];
    __shared__ float h2s[16][17];
    int tid = threadIdx.x;
    Ps[tid] = P[tid];
    int gid = blockIdx.x * 256 + tid;      // < ND*HID
    int i = gid >> 4, j = gid & 15;
    int il = tid >> 4, jl = tid & 15;
    float v = g_dinv[i] * g_agg[gid] + __ldg(b2 + j);
    g_h2[gid] = v;
    h2s[il][jl] = v;
    __syncthreads();
    float acc = 0.f;
#pragma unroll
    for (int k = 0; k < HID; k++) acc += h2s[il][k] * Ps[k * HID + j];
    g_tmp[gid] = acc;
}

// ---------------- out[i][j] = dot(tmp[i,:], h2[j,:]) ----------------
__global__ void k_out(float* __restrict__ out) {
    __shared__ float ts[16][17];
    __shared__ float hs[16][17];
    int tid = threadIdx.x;
    int il = tid >> 4, jl = tid & 15;
    int ib = blockIdx.y * 16, jb = blockIdx.x * 16;
    ts[il][jl] = g_tmp[(size_t)(ib + il) * HID + jl];
    hs[il][jl] = g_h2[(size_t)(jb + il) * HID + jl];
    __syncthreads();
    float acc = 0.f;
#pragma unroll
    for (int k = 0; k < HID; k++) acc += ts[il][k] * hs[jl][k];
    out[(size_t)(ib + il) * ND + jb + jl] = acc;
}

// ---------------- launch ----------------
extern "C" void kernel_launch(void* const* d_in, const int* in_sizes, int n_in,
                              void* d_out, int out_size) {
    (void)in_sizes; (void)n_in; (void)out_size;
    const float* x  = (const float*)d_in[0];
    const int*   ei = (const int*)  d_in[1];
    const float* W1 = (const float*)d_in[2];
    const float* b1 = (const float*)d_in[3];
    const float* W2 = (const float*)d_in[4];
    const float* b2 = (const float*)d_in[5];
    const float* P  = (const float*)d_in[6];
    float* out = (float*)d_out;

    const int* src = ei;
    const int* dst = ei + NE;

    k_init <<<(NN + 255) / 256, 256>>>();
    k_prep <<<NE / 4 / 256, 256>>>(src, dst);
    k_rsqrt<<<(NN + 255) / 256, 256>>>();

    // layer 1
    k_gemm1<<<(NN + 255) / 256, 256>>>(x, W1);
    k_edge1<<<(NE * 4) / 256, 256>>>(src, dst);

    // layer 2
    k_gemm2<<<(NN + 255) / 256, 256>>>(W2, b1);
    k_edge2<<<(NE * 4) / 256, 256>>>(src, dst);

    // decoder
    k_pred1<<<(ND * HID) / 256, 256>>>(P, b2);
    k_out  <<<dim3(ND / 16, ND / 16), 256>>>(out);
}